// round 1
// baseline (speedup 1.0000x reference)
#include <cuda_runtime.h>

// BarrierNet fused kernel: 5 -> 128 -> {32,32} -> {2,2} MLP + CBF-QP epilogue.
// fp32 throughout, packed fma.rn.f32x2 for 2x FMA-pipe throughput.
// One thread per row. Weights staged in SMEM (uniform-address broadcast loads).

__device__ __forceinline__ float2 ffma2(float2 a, float2 b, float2 c) {
    float2 d;
    asm("{\n\t"
        ".reg .b64 A,Bb,C,D;\n\t"
        "mov.b64 A,{%2,%3};\n\t"
        "mov.b64 Bb,{%4,%5};\n\t"
        "mov.b64 C,{%6,%7};\n\t"
        "fma.rn.f32x2 D,A,Bb,C;\n\t"
        "mov.b64 {%0,%1},D;\n\t"
        "}"
        : "=f"(d.x), "=f"(d.y)
        : "f"(a.x), "f"(a.y), "f"(b.x), "f"(b.y), "f"(c.x), "f"(c.y));
    return d;
}

__global__ __launch_bounds__(256) void barriernet_kernel(
    const float* __restrict__ x,
    const float* __restrict__ mean_, const float* __restrict__ std_,
    const float* __restrict__ w1,  const float* __restrict__ b1,
    const float* __restrict__ w21, const float* __restrict__ b21,
    const float* __restrict__ w22, const float* __restrict__ b22,
    const float* __restrict__ w31, const float* __restrict__ b31,
    const float* __restrict__ w32, const float* __restrict__ b32,
    float2* __restrict__ out, int B)
{
    // ---- shared staging ----
    __shared__ __align__(16) float s_w2[64][128];  // rows 0..31: fc21_w, 32..63: fc22_w
    __shared__ float2 s_w1p[5][64];                // s_w1p[i][jp] = (w1[2jp][i], w1[2jp+1][i])
    __shared__ float2 s_b1[64];
    __shared__ float  s_b2[64];
    __shared__ float2 s_w3[64];                    // o<32: (w31[0][o],w31[1][o]); o>=32: (w32[0][o-32],w32[1][o-32])
    __shared__ float  s_b3[4];                     // b31[0],b31[1],b32[0],b32[1]
    __shared__ float  s_mean[5], s_std[5];

    const int t = threadIdx.x;

    for (int idx = t; idx < 64 * 128; idx += 256) {
        int o = idx >> 7, k = idx & 127;
        s_w2[o][k] = (o < 32) ? w21[o * 128 + k] : w22[(o - 32) * 128 + k];
    }
    for (int idx = t; idx < 5 * 64; idx += 256) {
        int i = idx / 64, jp = idx % 64;
        s_w1p[i][jp] = make_float2(w1[(2 * jp) * 5 + i], w1[(2 * jp + 1) * 5 + i]);
    }
    if (t < 64) {
        s_b1[t] = make_float2(b1[2 * t], b1[2 * t + 1]);
        s_b2[t] = (t < 32) ? b21[t] : b22[t - 32];
        // w31/w32 are (2,32) row-major: w[j*32 + o]
        s_w3[t] = (t < 32) ? make_float2(w31[t], w31[32 + t])
                           : make_float2(w32[t - 32], w32[t]);  // w32[(t-32)], w32[32+(t-32)]
    }
    if (t < 4) s_b3[t] = (t < 2) ? b31[t] : b32[t - 2];
    if (t < 5) { s_mean[t] = mean_[t]; s_std[t] = std_[t]; }
    __syncthreads();

    const int row = blockIdx.x * 256 + t;
    if (row >= B) return;

    // ---- load input (raw x feeds the network; x0 feeds the physics) ----
    float xi[5];
#pragma unroll
    for (int i = 0; i < 5; i++) xi[i] = x[row * 5 + i];

    // ---- layer 1: h1 = relu(x @ w1^T + b1), 128 units as 64 float2 ----
    float2 h[64];
#pragma unroll
    for (int jp = 0; jp < 64; jp++) h[jp] = s_b1[jp];
#pragma unroll
    for (int i = 0; i < 5; i++) {
        float2 vv = make_float2(xi[i], xi[i]);
#pragma unroll
        for (int jp = 0; jp < 64; jp++) h[jp] = ffma2(vv, s_w1p[i][jp], h[jp]);
    }
#pragma unroll
    for (int jp = 0; jp < 64; jp++) {
        h[jp].x = fmaxf(h[jp].x, 0.f);
        h[jp].y = fmaxf(h[jp].y, 0.f);
    }

    // ---- layer 2 (64 hidden units across fc21|fc22) fused with layer 3 ----
    // u3a accumulates w31 @ relu(fc21 out); u3b accumulates w32 @ relu(fc22 out)
    float2 u3a = make_float2(0.f, 0.f);
    float2 u3b = make_float2(0.f, 0.f);

#pragma unroll
    for (int ob = 0; ob < 8; ob++) {
        float2 acc[8];
#pragma unroll
        for (int oi = 0; oi < 8; oi++) acc[oi] = make_float2(0.f, 0.f);
#pragma unroll
        for (int k4 = 0; k4 < 32; k4++) {
            float2 ha = h[2 * k4];
            float2 hb = h[2 * k4 + 1];
#pragma unroll
            for (int oi = 0; oi < 8; oi++) {
                const float4 w = *reinterpret_cast<const float4*>(&s_w2[ob * 8 + oi][k4 * 4]);
                acc[oi] = ffma2(ha, make_float2(w.x, w.y), acc[oi]);
                acc[oi] = ffma2(hb, make_float2(w.z, w.w), acc[oi]);
            }
        }
#pragma unroll
        for (int oi = 0; oi < 8; oi++) {
            int o = ob * 8 + oi;
            float y = fmaxf(acc[oi].x + acc[oi].y + s_b2[o], 0.f);
            float2 yy = make_float2(y, y);
            if (ob < 4) u3a = ffma2(yy, s_w3[o], u3a);
            else        u3b = ffma2(yy, s_w3[o], u3b);
        }
    }

    // ---- epilogue: CBF-QP ----
    float x0[4];
#pragma unroll
    for (int i = 0; i < 4; i++) x0[i] = xi[i] * s_std[i] + s_mean[i];

    const float px = x0[0], py = x0[1], th = x0[2], v = x0[3];
    float s, c;
    sincosf(th, &s, &c);
    const float dx = px - 40.0f;
    const float dy = py - 15.0f;
    const float barrier = dx * dx + dy * dy - 36.0f;               // R^2 = 36
    const float bdot    = 2.0f * dx * v * c + 2.0f * dy * v * s;
    const float Lf2b    = 2.0f * v * v;
    // G = [-LgLfbu1, -LgLfbu2]
    const float g1 = -(-2.0f * dx * v * s + 2.0f * dy * v * c);
    const float g2 = -(2.0f * dx * c + 2.0f * dy * s);

    // x31 = u3a + b31 ; u0 = -x31
    const float u0x = -(u3a.x + s_b3[0]);
    const float u0y = -(u3a.y + s_b3[1]);
    // x32 = 4 * sigmoid(u3b + b32)
    const float z1 = u3b.x + s_b3[2];
    const float z2 = u3b.y + s_b3[3];
    const float x32_0 = 4.0f / (1.0f + expf(-z1));
    const float x32_1 = 4.0f / (1.0f + expf(-z2));

    const float hq   = Lf2b + (x32_0 + x32_1) * bdot + x32_0 * x32_1 * barrier;
    const float viol = g1 * u0x + g2 * u0y - hq;
    const float gg   = g1 * g1 + g2 * g2;
    const float lam  = fmaxf(viol, 0.f) / (gg + 1e-12f);

    out[row] = make_float2(u0x - lam * g1, u0y - lam * g2);
}

extern "C" void kernel_launch(void* const* d_in, const int* in_sizes, int n_in,
                              void* d_out, int out_size) {
    const float* x    = (const float*)d_in[0];
    // d_in[1] = sgn (int32) — unused by the reference math
    const float* mean_ = (const float*)d_in[2];
    const float* std_  = (const float*)d_in[3];
    const float* w1   = (const float*)d_in[4];
    const float* b1   = (const float*)d_in[5];
    const float* w21  = (const float*)d_in[6];
    const float* b21  = (const float*)d_in[7];
    const float* w22  = (const float*)d_in[8];
    const float* b22  = (const float*)d_in[9];
    const float* w31  = (const float*)d_in[10];
    const float* b31  = (const float*)d_in[11];
    const float* w32  = (const float*)d_in[12];
    const float* b32  = (const float*)d_in[13];

    const int B = in_sizes[0] / 5;
    const int blocks = (B + 255) / 256;
    barriernet_kernel<<<blocks, 256>>>(x, mean_, std_, w1, b1, w21, b21,
                                       w22, b22, w31, b31, w32, b32,
                                       (float2*)d_out, B);
}

// round 2
// speedup vs baseline: 1.0660x; 1.0660x over previous
#include <cuda_runtime.h>

// BarrierNet fused: 5 -> 128 -> {32,32} -> {2,2} MLP + CBF-QP epilogue.
// R=2 rows/thread; layer-2 weights transposed in SMEM so each LDS.128 feeds
// 4 ffma2 (2 output-pairs x 2 rows). h1 is streamed (never materialized).

__device__ __forceinline__ float2 ffma2(float2 a, float2 b, float2 c) {
    float2 d;
    asm("{\n\t"
        ".reg .b64 A,Bb,C,D;\n\t"
        "mov.b64 A,{%2,%3};\n\t"
        "mov.b64 Bb,{%4,%5};\n\t"
        "mov.b64 C,{%6,%7};\n\t"
        "fma.rn.f32x2 D,A,Bb,C;\n\t"
        "mov.b64 {%0,%1},D;\n\t"
        "}"
        : "=f"(d.x), "=f"(d.y)
        : "f"(a.x), "f"(a.y), "f"(b.x), "f"(b.y), "f"(c.x), "f"(c.y));
    return d;
}

__global__ __launch_bounds__(128, 3) void barriernet_kernel(
    const float* __restrict__ x,
    const float* __restrict__ mean_, const float* __restrict__ std_,
    const float* __restrict__ w1,  const float* __restrict__ b1,
    const float* __restrict__ w21, const float* __restrict__ b21,
    const float* __restrict__ w22, const float* __restrict__ b22,
    const float* __restrict__ w31, const float* __restrict__ b31,
    const float* __restrict__ w32, const float* __restrict__ b32,
    float2* __restrict__ out, int B)
{
    __shared__ __align__(16) float s_w2t[128][64]; // [k][o] o<32: fc21, else fc22  (32KB)
    __shared__ __align__(16) float4 s_w1a[128];    // w1[j][0..3]
    __shared__ float2 s_w1b[128];                  // (w1[j][4], b1[j])
    __shared__ float2 s_b2p[32];                   // bias pairs of combined 64 outputs
    __shared__ float2 s_w3[64];                    // o<32:(w31[0][o],w31[1][o]) else w32
    __shared__ float  s_b3[4];
    __shared__ float  s_mean[4], s_std[4];

    const int t = threadIdx.x;

    // ---- stage weights ----
    for (int idx = t; idx < 128 * 64; idx += 128) {
        int k = idx >> 6, o = idx & 63;
        s_w2t[k][o] = (o < 32) ? w21[o * 128 + k] : w22[(o - 32) * 128 + k];
    }
    {
        s_w1a[t] = make_float4(w1[t * 5 + 0], w1[t * 5 + 1], w1[t * 5 + 2], w1[t * 5 + 3]);
        s_w1b[t] = make_float2(w1[t * 5 + 4], b1[t]);
    }
    if (t < 32) {
        s_b2p[t] = (t < 16) ? make_float2(b21[2 * t], b21[2 * t + 1])
                            : make_float2(b22[2 * (t - 16)], b22[2 * (t - 16) + 1]);
    }
    if (t < 64) {
        s_w3[t] = (t < 32) ? make_float2(w31[t], w31[32 + t])
                           : make_float2(w32[t - 32], w32[t]);
    }
    if (t < 4) { s_b3[t] = (t < 2) ? b31[t] : b32[t - 2]; s_mean[t] = mean_[t]; s_std[t] = std_[t]; }
    __syncthreads();

    const int r0 = blockIdx.x * 256 + t;
    const int r1 = r0 + 128;
    if (r1 >= B + 128) return;  // full blocks only (B divisible by 256 here)

    float xa[5], xb[5];
#pragma unroll
    for (int i = 0; i < 5; i++) { xa[i] = x[r0 * 5 + i]; xb[i] = x[r1 * 5 + i]; }

    // ---- fused layer1 (streamed) + layer2 accumulate ----
    float2 a0[32], a1[32];
#pragma unroll
    for (int o = 0; o < 32; o++) { a0[o] = make_float2(0.f, 0.f); a1[o] = make_float2(0.f, 0.f); }

#pragma unroll 4
    for (int k = 0; k < 128; k++) {
        const float4 wa = s_w1a[k];
        const float2 wb = s_w1b[k];
        float h0 = fmaf(xa[0], wa.x, fmaf(xa[1], wa.y, fmaf(xa[2], wa.z,
                   fmaf(xa[3], wa.w, fmaf(xa[4], wb.x, wb.y)))));
        float h1 = fmaf(xb[0], wa.x, fmaf(xb[1], wa.y, fmaf(xb[2], wa.z,
                   fmaf(xb[3], wa.w, fmaf(xb[4], wb.x, wb.y)))));
        h0 = fmaxf(h0, 0.f);
        h1 = fmaxf(h1, 0.f);
        const float2 H0 = make_float2(h0, h0);
        const float2 H1 = make_float2(h1, h1);
#pragma unroll
        for (int o4 = 0; o4 < 16; o4++) {
            const float4 w = *reinterpret_cast<const float4*>(&s_w2t[k][o4 * 4]);
            const float2 wlo = make_float2(w.x, w.y);
            const float2 whi = make_float2(w.z, w.w);
            a0[2 * o4]     = ffma2(H0, wlo, a0[2 * o4]);
            a0[2 * o4 + 1] = ffma2(H0, whi, a0[2 * o4 + 1]);
            a1[2 * o4]     = ffma2(H1, wlo, a1[2 * o4]);
            a1[2 * o4 + 1] = ffma2(H1, whi, a1[2 * o4 + 1]);
        }
    }

    // ---- per-row: layer-2 bias+relu, layer-3, CBF-QP epilogue ----
#pragma unroll
    for (int r = 0; r < 2; r++) {
        const float2* acc = r ? a1 : a0;
        const float*  xi  = r ? xb : xa;
        const int     row = r ? r1 : r0;

        float2 u3a = make_float2(0.f, 0.f);
        float2 u3b = make_float2(0.f, 0.f);
#pragma unroll
        for (int o2 = 0; o2 < 32; o2++) {
            const float2 bp = s_b2p[o2];
            const float y0 = fmaxf(acc[o2].x + bp.x, 0.f);
            const float y1 = fmaxf(acc[o2].y + bp.y, 0.f);
            if (o2 < 16) {
                u3a = ffma2(make_float2(y0, y0), s_w3[2 * o2],     u3a);
                u3a = ffma2(make_float2(y1, y1), s_w3[2 * o2 + 1], u3a);
            } else {
                u3b = ffma2(make_float2(y0, y0), s_w3[2 * o2],     u3b);
                u3b = ffma2(make_float2(y1, y1), s_w3[2 * o2 + 1], u3b);
            }
        }

        const float px = xi[0] * s_std[0] + s_mean[0];
        const float py = xi[1] * s_std[1] + s_mean[1];
        const float th = xi[2] * s_std[2] + s_mean[2];
        const float v  = xi[3] * s_std[3] + s_mean[3];
        float s, c;
        sincosf(th, &s, &c);
        const float dx = px - 40.0f;
        const float dy = py - 15.0f;
        const float barrier = dx * dx + dy * dy - 36.0f;
        const float bdot    = 2.0f * dx * v * c + 2.0f * dy * v * s;
        const float Lf2b    = 2.0f * v * v;
        const float g1 = -(-2.0f * dx * v * s + 2.0f * dy * v * c);
        const float g2 = -(2.0f * dx * c + 2.0f * dy * s);

        const float u0x = -(u3a.x + s_b3[0]);
        const float u0y = -(u3a.y + s_b3[1]);
        const float z1 = u3b.x + s_b3[2];
        const float z2 = u3b.y + s_b3[3];
        const float x32_0 = 4.0f / (1.0f + expf(-z1));
        const float x32_1 = 4.0f / (1.0f + expf(-z2));

        const float hq   = Lf2b + (x32_0 + x32_1) * bdot + x32_0 * x32_1 * barrier;
        const float viol = g1 * u0x + g2 * u0y - hq;
        const float gg   = g1 * g1 + g2 * g2;
        const float lam  = fmaxf(viol, 0.f) / (gg + 1e-12f);

        out[row] = make_float2(u0x - lam * g1, u0y - lam * g2);
    }
}

extern "C" void kernel_launch(void* const* d_in, const int* in_sizes, int n_in,
                              void* d_out, int out_size) {
    const float* x     = (const float*)d_in[0];
    const float* mean_ = (const float*)d_in[2];
    const float* std_  = (const float*)d_in[3];
    const float* w1    = (const float*)d_in[4];
    const float* b1    = (const float*)d_in[5];
    const float* w21   = (const float*)d_in[6];
    const float* b21   = (const float*)d_in[7];
    const float* w22   = (const float*)d_in[8];
    const float* b22   = (const float*)d_in[9];
    const float* w31   = (const float*)d_in[10];
    const float* b31   = (const float*)d_in[11];
    const float* w32   = (const float*)d_in[12];
    const float* b32   = (const float*)d_in[13];

    const int B = in_sizes[0] / 5;
    const int blocks = (B + 255) / 256;  // 2 rows per thread, 128 threads
    barriernet_kernel<<<blocks, 128>>>(x, mean_, std_, w1, b1, w21, b21,
                                       w22, b22, w31, b31, w32, b32,
                                       (float2*)d_out, B);
}